// round 15
// baseline (speedup 1.0000x reference)
#include <cuda_runtime.h>
#include <cuda_fp16.h>
#include <cuda_bf16.h>
#include <cstdint>

// ---------------- problem constants ----------------
#define NB   64
#define NT   256
#define NC   256
#define HW   4096
#define NITER 30

#define K2C     28.853900817779268f   // log2(e)/eps
#define INV_K2  0.03465735902799727f  // eps*ln2
#define SHIFTF  26.0f
#define MUC     (1.0f/256.0f)

// ---------------- scratch ----------------
__device__ __align__(16) __nv_bfloat16 g_tok[(size_t)2 * NB * NT * NC];  // [z][b][i][c] RAW
__device__ __align__(16) float         g_pss[(size_t)2 * NB * NT * 2];   // [z][b][i][half]
__device__ __align__(16) __half        g_K[(size_t)NB * NT * NT];
__device__ float    g_part[2 * NB];
__device__ unsigned g_ctr;

__device__ __forceinline__ uint32_t smem_u32(const void* p) {
    uint32_t a;
    asm("{ .reg .u64 t; cvta.to.shared.u64 t, %1; cvt.u32.u64 %0, t; }" : "=r"(a) : "l"(p));
    return a;
}
__device__ __forceinline__ uint32_t h2_as_u32(__half lo, __half hi) {
    union { __half2 h; uint32_t u; } c;
    c.h = __halves2half2(lo, hi);
    return c.u;
}

// ============================================================================
// Kernel 1: streaming sampler, 2 CTAs per (b,z) plane -> 256 CTAs (no idle SMs).
// CTA = (b, z, half): streams 128 channels (2MB) coalesced, stages samples in
// smem [128c][264], writes RAW token-major bf16 slice + per-token partial
// sum-of-squares. Norms are applied in the cost kernel epilogue.
// ============================================================================
#define TSTR 264
#define GK_SMEM (128 * TSTR * 2 + 4096)

__global__ __launch_bounds__(1024, 1) void gather_kernel(
    const float* __restrict__ pred, const float* __restrict__ tgt)
{
    extern __shared__ unsigned char sm[];
    __nv_bfloat16* T = (__nv_bfloat16*)sm;               // [128 c][264] swizzled
    float* pss = (float*)(sm + 128 * TSTR * 2);          // [4][256]

    const int b = blockIdx.x, z = blockIdx.y, hf = blockIdx.z;
    if (threadIdx.x == 0 && (b | z | hf) == 0) g_ctr = 0u;
    const int tid = threadIdx.x;
    const float DELTA = 4095.0f / 255.0f;

    const float4* __restrict__ src =
        (const float4*)((z ? tgt : pred) + ((size_t)b * NC + hf * 128) * HW);

    // thread tid owns float4 slot tid of every channel: window [tid*4, tid*4+4)
    const int p4 = tid * 4;
    const int cand = (int)(__fdividef((float)(p4 + 2), DELTA));
    int hit_i = -1, hit_off = 0;
    #pragma unroll
    for (int d = -1; d <= 1; ++d) {
        const int i = cand + d;
        if (i >= 0 && i < 256) {
            const int s = (int)(__fmul_rn((float)i, DELTA));  // exact ref trunc
            if (s >= p4 && s < p4 + 4) { hit_i = i; hit_off = s - p4; }
        }
    }
    const int ibs = (hit_i >= 0) ? (hit_i >> 3) : 0;
    const int ios = (hit_i >= 0) ? (hit_i & 7) : 0;

    #pragma unroll 2
    for (int c4 = 0; c4 < 128; c4 += 4) {
        float4 f[4];
        #pragma unroll
        for (int q = 0; q < 4; ++q) f[q] = __ldcs(&src[(size_t)(c4 + q) * 1024 + tid]);
        if (hit_i >= 0) {
            #pragma unroll
            for (int q = 0; q < 4; ++q) {
                const int c = c4 + q;                        // local channel 0..127
                const float* fv = (const float*)&f[q];
                T[c * TSTR + ((ibs ^ ((c >> 3) & 7)) << 3) + ios] =
                    __float2bfloat16(fv[hit_off]);
            }
        }
    }
    __syncthreads();

    {   // partial sum of squares per token over this CTA's 128 channels
        const int i = tid & 255, part = tid >> 8;
        const int ib = i >> 3, io = i & 7;
        float ss = 0.0f;
        #pragma unroll 8
        for (int cc = 0; cc < 32; ++cc) {
            const int c = part * 32 + cc;
            const float x = __bfloat162float(
                T[c * TSTR + ((ib ^ ((c >> 3) & 7)) << 3) + io]);
            ss = fmaf(x, x, ss);
        }
        pss[part * 256 + i] = ss;
    }
    __syncthreads();
    if (tid < 256) {
        g_pss[(((size_t)z * NB + b) * NT + tid) * 2 + hf] =
            (pss[tid] + pss[256 + tid]) + (pss[512 + tid] + pss[768 + tid]);
    }

    // RAW token-major write: 256 tokens x 128 ch bf16 = 4096 uint4, 4/thread
    __nv_bfloat16* __restrict__ dst =
        g_tok + ((size_t)z * NB + b) * NT * NC + hf * 128;
    #pragma unroll
    for (int k = 0; k < 4; ++k) {
        const int idx = tid + k * 1024;
        const int i = idx >> 4, c0 = (idx & 15) * 8;   // local channel group
        const int ib = i >> 3, io = i & 7;
        union { uint4 u; __nv_bfloat16 h[8]; } o;
        #pragma unroll
        for (int j = 0; j < 8; ++j) {
            const int c = c0 + j;
            o.h[j] = T[c * TSTR + ((ib ^ ((c >> 3) & 7)) << 3) + io];
        }
        *(uint4*)(dst + (size_t)i * NC + c0) = o.u;
    }
}

// ============================================================================
// Kernel 2: cost GEMM via mma.sync bf16 on RAW tokens; norms applied in the
// epilogue: dotn = dot * invp[m] * invt[n];  K' = exp2((dotn-1)*K2C + 26).
// ============================================================================
#define SPAD 264
#define COST_SMEM ((128 + 256) * SPAD * 2 + (128 + 256) * 4)

__device__ __forceinline__ void mma16816bf(float* c, uint32_t a0, uint32_t a1,
                                           uint32_t a2, uint32_t a3,
                                           uint32_t b0, uint32_t b1) {
    asm volatile(
        "mma.sync.aligned.m16n8k16.row.col.f32.bf16.bf16.f32 "
        "{%0,%1,%2,%3}, {%4,%5,%6,%7}, {%8,%9}, {%0,%1,%2,%3};"
        : "+f"(c[0]), "+f"(c[1]), "+f"(c[2]), "+f"(c[3])
        : "r"(a0), "r"(a1), "r"(a2), "r"(a3), "r"(b0), "r"(b1));
}

__global__ __launch_bounds__(256, 1) void cost_kernel()
{
    extern __shared__ char smem[];
    __nv_bfloat16* As = (__nv_bfloat16*)smem;
    __nv_bfloat16* Bs = (__nv_bfloat16*)(smem + 128 * SPAD * 2);
    float* invp = (float*)(smem + (128 + 256) * SPAD * 2);   // [128]
    float* invt = invp + 128;                                 // [256]

    const int mh = blockIdx.x;
    const int b  = blockIdx.y;
    const int tid = threadIdx.x, w = tid >> 5, lane = tid & 31;

    // ---- inverse norms from g_pss partials (fixed order: hf0 + hf1)
    if (tid < 128) {
        const float* ps = g_pss + (((size_t)b) * NT + mh * 128 + tid) * 2;
        invp[tid] = __fdividef(1.0f, fmaxf(sqrtf(ps[0] + ps[1]), 1e-12f));
    }
    {
        const float* ps = g_pss + (((size_t)NB + b) * NT + tid) * 2;
        invt[tid] = __fdividef(1.0f, fmaxf(sqrtf(ps[0] + ps[1]), 1e-12f));
    }

    const uint4* __restrict__ Ag =
        (const uint4*)(g_tok + ((size_t)b * NT + (size_t)mh * 128) * NC);
    #pragma unroll
    for (int it = 0; it < 16; ++it) {
        const int idx = tid + it * 256;
        *(uint4*)(As + (idx >> 5) * SPAD + (idx & 31) * 8) = Ag[idx];
    }
    const uint4* __restrict__ Bg = (const uint4*)(g_tok + ((size_t)(NB + b)) * NT * NC);
    #pragma unroll
    for (int it = 0; it < 32; ++it) {
        const int idx = tid + it * 256;
        *(uint4*)(Bs + (idx >> 5) * SPAD + (idx & 31) * 8) = Bg[idx];
    }
    __syncthreads();

    const int r0 = w * 16;
    const int lr = lane >> 2;
    const int lj = lane & 3;

    const __nv_bfloat16* A0 = As + (r0 + lr) * SPAD + lj * 2;
    const __nv_bfloat16* A8 = A0 + 8 * SPAD;
    const __nv_bfloat16* B0 = Bs + lr * SPAD + lj * 2;

    __half* __restrict__ K0 = g_K + ((size_t)b * NT + (size_t)(mh * 128 + r0 + lr)) * NT;
    __half* __restrict__ K8 = K0 + 8 * NT;
    const float ip0 = invp[r0 + lr];
    const float ip8 = invp[r0 + 8 + lr];

    #pragma unroll
    for (int h = 0; h < 2; ++h) {
        float c[16][4];
        #pragma unroll
        for (int nt = 0; nt < 16; ++nt)
            c[nt][0] = c[nt][1] = c[nt][2] = c[nt][3] = 0.0f;

        #pragma unroll
        for (int kc = 0; kc < 16; ++kc) {
            const int ko = kc * 16;
            const uint32_t a0 = *(const uint32_t*)(A0 + ko);
            const uint32_t a1 = *(const uint32_t*)(A8 + ko);
            const uint32_t a2 = *(const uint32_t*)(A0 + ko + 8);
            const uint32_t a3 = *(const uint32_t*)(A8 + ko + 8);
            #pragma unroll
            for (int nt = 0; nt < 16; ++nt) {
                const __nv_bfloat16* bp = B0 + (h * 128 + nt * 8) * SPAD + ko;
                mma16816bf(c[nt], a0, a1, a2, a3,
                           *(const uint32_t*)bp, *(const uint32_t*)(bp + 8));
            }
        }

        #pragma unroll
        for (int nt = 0; nt < 16; ++nt) {
            const int col = h * 128 + nt * 8 + lj * 2;
            const float it0 = invt[col], it1 = invt[col + 1];
            const float d00 = c[nt][0] * ip0 * it0, d01 = c[nt][1] * ip0 * it1;
            const float d80 = c[nt][2] * ip8 * it0, d81 = c[nt][3] * ip8 * it1;
            *(__half2*)(K0 + col) = __halves2half2(
                __float2half_rn(exp2f(fmaf(d00 - 1.0f, K2C, SHIFTF))),
                __float2half_rn(exp2f(fmaf(d01 - 1.0f, K2C, SHIFTF))));
            *(__half2*)(K8 + col) = __halves2half2(
                __float2half_rn(exp2f(fmaf(d80 - 1.0f, K2C, SHIFTF))),
                __float2half_rn(exp2f(fmaf(d81 - 1.0f, K2C, SHIFTF))));
        }
    }
}

// ============================================================================
// Kernel 3: Sinkhorn, warp-specialized, K^T v-pass (round-14 exact).
// ============================================================================
#define SK_KS    0
#define SK_RECV  65536                 // [2][256] f32 peer-pushed colsums
#define SK_V     (SK_RECV + 2048)      // [256] f32
#define SK_U     (SK_V + 1024)         // [128] f32
#define SK_UH    (SK_U + 512)          // [128] f16 (scaled x64)
#define SK_VH    (SK_UH + 256)         // [256] f16
#define SK_RED   (SK_VH + 512)         // [16] f32 (pad)
#define SK_MBAR  (SK_RED + 128)
#define SK_SMEM  (SK_MBAR + 16)

__device__ __forceinline__ void mma16816f(float* c, uint32_t a0, uint32_t a1,
                                          uint32_t a2, uint32_t a3,
                                          uint32_t b0, uint32_t b1) {
    asm volatile(
        "mma.sync.aligned.m16n8k16.row.col.f32.f16.f16.f32 "
        "{%0,%1,%2,%3}, {%4,%5,%6,%7}, {%8,%9}, {%0,%1,%2,%3};"
        : "+f"(c[0]), "+f"(c[1]), "+f"(c[2]), "+f"(c[3])
        : "r"(a0), "r"(a1), "r"(a2), "r"(a3), "r"(b0), "r"(b1));
}

__global__ __launch_bounds__(512, 1) __cluster_dims__(2, 1, 1)
void sinkhorn_kernel(float* __restrict__ out)
{
    extern __shared__ unsigned char sm[];
    __half* Ks   = (__half*)(sm + SK_KS);      // [128][256] local rows
    float*  recv = (float*)(sm + SK_RECV);
    float*  v    = (float*)(sm + SK_V);
    float*  u    = (float*)(sm + SK_U);
    __half* uh   = (__half*)(sm + SK_UH);
    __half* vh   = (__half*)(sm + SK_VH);
    float*  red  = (float*)(sm + SK_RED);

    const int rank = blockIdx.x & 1;
    const int b    = blockIdx.x >> 1;
    const int tid  = threadIdx.x;
    const int w    = tid >> 5, lane = tid & 31;
    const int lr4  = lane >> 2, lj = lane & 3;

    const uint32_t mbar_local = smem_u32(sm + SK_MBAR);
    uint32_t recv_peer, mbar_peer;
    {
        const uint32_t recv_local = smem_u32(recv);
        asm("mapa.shared::cluster.u32 %0, %1, %2;" : "=r"(recv_peer)
            : "r"(recv_local), "r"(rank ^ 1));
        asm("mapa.shared::cluster.u32 %0, %1, %2;" : "=r"(mbar_peer)
            : "r"(mbar_local), "r"(rank ^ 1));
    }

    if (tid == 0) {
        asm volatile("mbarrier.init.shared.b64 [%0], %1;"
                     :: "r"(mbar_local), "r"(64u) : "memory");
    }

    {   // load my 128 rows of K' (64 KB)
        const uint4* gk = (const uint4*)(g_K + ((size_t)b * NT + (size_t)rank * 128) * NT);
        uint4* sk = (uint4*)Ks;
        #pragma unroll
        for (int q = 0; q < 8; ++q) sk[tid + q * 512] = gk[tid + q * 512];
    }
    if (tid < NT) { v[tid] = 1.0f; vh[tid] = __float2half_rn(1.0f); }
    __syncthreads();

    // cluster sync once: peer mbarrier init visible before any remote push
    asm volatile("barrier.cluster.arrive.aligned;" ::: "memory");
    asm volatile("barrier.cluster.wait.aligned;" ::: "memory");

    // ---- role-shared fragment storage (disjoint indexing per role) ----
    uint32_t frag[64];
    const bool roww = (w < 8);
    const int rt = w;           // row warp: rows rt*16..+15
    const int wc = w - 8;       // col warp: m-tiles (cols) 2wc, 2wc+1

    if (roww) {
        #pragma unroll
        for (int t = 0; t < 16; ++t) {
            const int kt = t * 16 + 2 * lj;
            frag[t*4+0] = *(const uint32_t*)&Ks[(rt * 16 + lr4) * NT + kt];
            frag[t*4+1] = *(const uint32_t*)&Ks[(rt * 16 + 8 + lr4) * NT + kt];
            frag[t*4+2] = *(const uint32_t*)&Ks[(rt * 16 + lr4) * NT + kt + 8];
            frag[t*4+3] = *(const uint32_t*)&Ks[(rt * 16 + 8 + lr4) * NT + kt + 8];
        }
    } else {
        #pragma unroll
        for (int mt = 0; mt < 2; ++mt) {
            const int j0 = (2 * wc + mt) * 16 + lr4;
            const int j1 = j0 + 8;
            #pragma unroll
            for (int t = 0; t < 8; ++t) {
                const int k0 = t * 16 + 2 * lj;
                frag[(mt*8+t)*4+0] = h2_as_u32(Ks[(size_t)k0 * NT + j0],
                                               Ks[(size_t)(k0 + 1) * NT + j0]);
                frag[(mt*8+t)*4+1] = h2_as_u32(Ks[(size_t)k0 * NT + j1],
                                               Ks[(size_t)(k0 + 1) * NT + j1]);
                frag[(mt*8+t)*4+2] = h2_as_u32(Ks[(size_t)(k0 + 8) * NT + j0],
                                               Ks[(size_t)(k0 + 9) * NT + j0]);
                frag[(mt*8+t)*4+3] = h2_as_u32(Ks[(size_t)(k0 + 8) * NT + j1],
                                               Ks[(size_t)(k0 + 9) * NT + j1]);
            }
        }
    }

    for (int it = 0; it < NITER; ++it) {
        __syncthreads();   // vh(it) visible to row warps
        if (roww) {
            float cc[4][4] = {};
            #pragma unroll
            for (int t = 0; t < 16; t += 4) {
                #pragma unroll
                for (int q = 0; q < 4; ++q) {
                    const int kt = (t + q) * 16 + 2 * lj;
                    mma16816f(cc[q],
                              frag[(t+q)*4+0], frag[(t+q)*4+1],
                              frag[(t+q)*4+2], frag[(t+q)*4+3],
                              *(const uint32_t*)&vh[kt],
                              *(const uint32_t*)&vh[kt + 8]);
                }
            }
            if (lj == 0) {
                const float s0 = (cc[0][0] + cc[1][0]) + (cc[2][0] + cc[3][0]);
                const float s2 = (cc[0][2] + cc[1][2]) + (cc[2][2] + cc[3][2]);
                const float u0 = __fdividef(MUC, s0);
                const float u2 = __fdividef(MUC, s2);
                const int i0 = rt * 16 + lr4;
                u[i0] = u0;      uh[i0] = __float2half_rn(u0 * 64.0f);
                u[i0 + 8] = u2;  uh[i0 + 8] = __float2half_rn(u2 * 64.0f);
            }
        }
        __syncthreads();   // uh visible to col warps
        if (!roww) {
            const int buf = it & 1;
            float cc[2][4] = {};
            #pragma unroll
            for (int t = 0; t < 8; ++t) {
                const int k0 = t * 16 + 2 * lj;
                const uint32_t b0 = *(const uint32_t*)&uh[k0];
                const uint32_t b1 = *(const uint32_t*)&uh[k0 + 8];
                #pragma unroll
                for (int mt = 0; mt < 2; ++mt)
                    mma16816f(cc[mt],
                              frag[(mt*8+t)*4+0], frag[(mt*8+t)*4+1],
                              frag[(mt*8+t)*4+2], frag[(mt*8+t)*4+3],
                              b0, b1);
            }
            if (lj == 0) {
                #pragma unroll
                for (int mt = 0; mt < 2; ++mt) {
                    const int j0 = (2 * wc + mt) * 16 + lr4;
                    asm volatile("st.shared::cluster.b32 [%0], %1;"
                                 :: "r"(recv_peer + (uint32_t)((buf * NT + j0) * 4)),
                                    "f"(cc[mt][0]) : "memory");
                    asm volatile("st.shared::cluster.b32 [%0], %1;"
                                 :: "r"(recv_peer + (uint32_t)((buf * NT + j0 + 8) * 4)),
                                    "f"(cc[mt][2]) : "memory");
                }
                asm volatile("mbarrier.arrive.release.cluster.shared::cluster.b64 _, [%0];"
                             :: "r"(mbar_peer) : "memory");
                uint32_t done;
                asm volatile("{ .reg .pred p; "
                             "mbarrier.try_wait.parity.acquire.cluster.shared::cta.b64 p, [%1], %2; "
                             "selp.b32 %0, 1, 0, p; }"
                             : "=r"(done) : "r"(mbar_local), "r"((uint32_t)buf) : "memory");
                while (!done) {
                    asm volatile("{ .reg .pred p; "
                                 "mbarrier.try_wait.parity.acquire.cluster.shared::cta.b64 p, [%1], %2, 0x989680; "
                                 "selp.b32 %0, 1, 0, p; }"
                                 : "=r"(done) : "r"(mbar_local), "r"((uint32_t)buf) : "memory");
                }
                #pragma unroll
                for (int mt = 0; mt < 2; ++mt) {
                    const int j0 = (2 * wc + mt) * 16 + lr4;
                    const float p0 = recv[buf * NT + j0];
                    const float p1 = recv[buf * NT + j0 + 8];
                    const float s0 = rank == 0 ? (cc[mt][0] + p0) : (p0 + cc[mt][0]);
                    const float s1 = rank == 0 ? (cc[mt][2] + p1) : (p1 + cc[mt][2]);
                    const float nv0 = __fdividef(0.25f, s0);   // MUC*64 (uh scale cancels)
                    const float nv1 = __fdividef(0.25f, s1);
                    v[j0] = nv0;     vh[j0] = __float2half_rn(nv0);
                    v[j0 + 8] = nv1; vh[j0 + 8] = __float2half_rn(nv1);
                }
            }
        }
    }
    __syncthreads();   // final u, v visible to all

    // ---- transport loss over my 128 rows (warp w -> rows 8w..8w+7)
    float vl[8];
    {
        const float4 v0 = *(const float4*)&v[lane * 8];
        const float4 v1 = *(const float4*)&v[lane * 8 + 4];
        vl[0]=v0.x; vl[1]=v0.y; vl[2]=v0.z; vl[3]=v0.w;
        vl[4]=v1.x; vl[5]=v1.y; vl[6]=v1.z; vl[7]=v1.w;
    }
    float acc = 0.0f;
    #pragma unroll
    for (int r = 0; r < 8; ++r) {
        const int i = w * 8 + r;
        const float ui = u[i];
        const uint4 kw = *(const uint4*)(Ks + (size_t)i * NT + lane * 8);
        float kf[8];
        {
            float2 f;
            f = __half22float2(*(const __half2*)&kw.x); kf[0]=f.x; kf[1]=f.y;
            f = __half22float2(*(const __half2*)&kw.y); kf[2]=f.x; kf[3]=f.y;
            f = __half22float2(*(const __half2*)&kw.z); kf[4]=f.x; kf[5]=f.y;
            f = __half22float2(*(const __half2*)&kw.w); kf[6]=f.x; kf[7]=f.y;
        }
        #pragma unroll
        for (int q = 0; q < 8; ++q) {
            const float k = kf[q];
            if (k > 0.0f) {
                const float cost = (SHIFTF - __log2f(k)) * INV_K2;  // == 1 - dot
                acc = fmaf(ui * k * vl[q], cost, acc);
            }
        }
    }
    #pragma unroll
    for (int o = 16; o; o >>= 1) acc += __shfl_xor_sync(0xffffffffu, acc, o);
    if (lane == 0) red[w] = acc;
    __syncthreads();
    if (w == 0) {
        float s = (lane < 16) ? red[lane] : 0.0f;
        #pragma unroll
        for (int o = 16; o; o >>= 1) s += __shfl_xor_sync(0xffffffffu, s, o);
        if (lane == 0) {
            g_part[blockIdx.x] = s;
            __threadfence();
            if (atomicAdd(&g_ctr, 1u) == 2 * NB - 1) {   // last CTA: deterministic mean
                __threadfence();
                float tot = 0.0f;
                #pragma unroll
                for (int i = 0; i < 2 * NB; ++i) tot += __ldcg(&g_part[i]);
                out[0] = tot * (1.0f / NB);
            }
        }
    }
    // no CTA may exit while peer pushes could still target its smem
    asm volatile("barrier.cluster.arrive.aligned;" ::: "memory");
    asm volatile("barrier.cluster.wait.aligned;" ::: "memory");
}

// ============================================================================
extern "C" void kernel_launch(void* const* d_in, const int* in_sizes, int n_in,
                              void* d_out, int out_size)
{
    const float* pred = (const float*)d_in[0];
    const float* tgt  = (const float*)d_in[1];
    float* out = (float*)d_out;

    cudaFuncSetAttribute(gather_kernel, cudaFuncAttributeMaxDynamicSharedMemorySize, GK_SMEM);
    gather_kernel<<<dim3(NB, 2, 2), 1024, GK_SMEM>>>(pred, tgt);

    cudaFuncSetAttribute(cost_kernel, cudaFuncAttributeMaxDynamicSharedMemorySize, COST_SMEM);
    cost_kernel<<<dim3(2, NB), 256, COST_SMEM>>>();

    cudaFuncSetAttribute(sinkhorn_kernel, cudaFuncAttributeMaxDynamicSharedMemorySize, SK_SMEM);
    sinkhorn_kernel<<<2 * NB, 512, SK_SMEM>>>(out);
}

// round 16
// speedup vs baseline: 1.0114x; 1.0114x over previous
#include <cuda_runtime.h>
#include <cuda_fp16.h>
#include <cuda_bf16.h>
#include <cstdint>

// ---------------- problem constants ----------------
#define NB   64
#define NT   256
#define NC   256
#define HW   4096
#define NITER 30

#define K2C     28.853900817779268f   // log2(e)/eps
#define INV_K2  0.03465735902799727f  // eps*ln2
#define SHIFTF  26.0f
#define MUC     (1.0f/256.0f)

// ---------------- scratch ----------------
__device__ __align__(16) __nv_bfloat16 g_tok[(size_t)2 * NB * NT * NC];  // [z][b][i][c] RAW
__device__ __align__(16) float         g_pss[(size_t)2 * NB * NT * 2];   // [z][b][i][half]
__device__ float    g_part[2 * NB];
__device__ unsigned g_ctr;

__device__ __forceinline__ uint32_t smem_u32(const void* p) {
    uint32_t a;
    asm("{ .reg .u64 t; cvta.to.shared.u64 t, %1; cvt.u32.u64 %0, t; }" : "=r"(a) : "l"(p));
    return a;
}
__device__ __forceinline__ uint32_t h2_as_u32(__half lo, __half hi) {
    union { __half2 h; uint32_t u; } c;
    c.h = __halves2half2(lo, hi);
    return c.u;
}

// ============================================================================
// Kernel 1: streaming sampler (round-15 exact; at the HBM floor).
// ============================================================================
#define TSTR 264
#define GK_SMEM (128 * TSTR * 2 + 4096)

__global__ __launch_bounds__(1024, 1) void gather_kernel(
    const float* __restrict__ pred, const float* __restrict__ tgt)
{
    extern __shared__ unsigned char sm[];
    __nv_bfloat16* T = (__nv_bfloat16*)sm;               // [128 c][264] swizzled
    float* pss = (float*)(sm + 128 * TSTR * 2);          // [4][256]

    const int b = blockIdx.x, z = blockIdx.y, hf = blockIdx.z;
    if (threadIdx.x == 0 && (b | z | hf) == 0) g_ctr = 0u;
    const int tid = threadIdx.x;
    const float DELTA = 4095.0f / 255.0f;

    const float4* __restrict__ src =
        (const float4*)((z ? tgt : pred) + ((size_t)b * NC + hf * 128) * HW);

    const int p4 = tid * 4;
    const int cand = (int)(__fdividef((float)(p4 + 2), DELTA));
    int hit_i = -1, hit_off = 0;
    #pragma unroll
    for (int d = -1; d <= 1; ++d) {
        const int i = cand + d;
        if (i >= 0 && i < 256) {
            const int s = (int)(__fmul_rn((float)i, DELTA));  // exact ref trunc
            if (s >= p4 && s < p4 + 4) { hit_i = i; hit_off = s - p4; }
        }
    }
    const int ibs = (hit_i >= 0) ? (hit_i >> 3) : 0;
    const int ios = (hit_i >= 0) ? (hit_i & 7) : 0;

    #pragma unroll 2
    for (int c4 = 0; c4 < 128; c4 += 4) {
        float4 f[4];
        #pragma unroll
        for (int q = 0; q < 4; ++q) f[q] = __ldcs(&src[(size_t)(c4 + q) * 1024 + tid]);
        if (hit_i >= 0) {
            #pragma unroll
            for (int q = 0; q < 4; ++q) {
                const int c = c4 + q;
                const float* fv = (const float*)&f[q];
                T[c * TSTR + ((ibs ^ ((c >> 3) & 7)) << 3) + ios] =
                    __float2bfloat16(fv[hit_off]);
            }
        }
    }
    __syncthreads();

    {
        const int i = tid & 255, part = tid >> 8;
        const int ib = i >> 3, io = i & 7;
        float ss = 0.0f;
        #pragma unroll 8
        for (int cc = 0; cc < 32; ++cc) {
            const int c = part * 32 + cc;
            const float x = __bfloat162float(
                T[c * TSTR + ((ib ^ ((c >> 3) & 7)) << 3) + io]);
            ss = fmaf(x, x, ss);
        }
        pss[part * 256 + i] = ss;
    }
    __syncthreads();
    if (tid < 256) {
        g_pss[(((size_t)z * NB + b) * NT + tid) * 2 + hf] =
            (pss[tid] + pss[256 + tid]) + (pss[512 + tid] + pss[768 + tid]);
    }

    __nv_bfloat16* __restrict__ dst =
        g_tok + ((size_t)z * NB + b) * NT * NC + hf * 128;
    #pragma unroll
    for (int k = 0; k < 4; ++k) {
        const int idx = tid + k * 1024;
        const int i = idx >> 4, c0 = (idx & 15) * 8;
        const int ib = i >> 3, io = i & 7;
        union { uint4 u; __nv_bfloat16 h[8]; } o;
        #pragma unroll
        for (int j = 0; j < 8; ++j) {
            const int c = c0 + j;
            o.h[j] = T[c * TSTR + ((ib ^ ((c >> 3) & 7)) << 3) + io];
        }
        *(uint4*)(dst + (size_t)i * NC + c0) = o.u;
    }
}

// ============================================================================
// Kernel 2: FUSED cost GEMM + Sinkhorn.  CTA (b, rank), cluster 2, 512 thr.
// Prologue computes K' rows rank*128..+128 directly into smem Ks (two 128-col
// half-phases over the B tile; epilogue norms via g_pss), then the
// warp-specialized sinkhorn runs on Ks with zero DRAM round-trip.
// ============================================================================
#define SPAD 264
#define SK_KS    0                       // 65536: K' [128][256] f16
#define SK_RECV  65536                   // 2048: [2][256] f32 peer colsums
#define SK_V     (SK_RECV + 2048)        // 1024
#define SK_U     (SK_V + 1024)           // 512
#define SK_UH    (SK_U + 512)            // 256 (scaled x64)
#define SK_VH    (SK_UH + 256)           // 512
#define SK_RED   (SK_VH + 512)           // 128
#define SK_MBAR  (SK_RED + 128)          // 16
#define SK_INVP  (SK_MBAR + 16)          // 512: [128] f32
#define SK_INVT  (SK_INVP + 512)         // 1024: [256] f32
#define SK_A     (SK_INVT + 1024)        // 67584: A tile [128][264] bf16
#define SK_B     (SK_A + 128 * SPAD * 2) // 67584: B half [128][264] bf16
#define SK_SMEM  (SK_B + 128 * SPAD * 2) // 206736

__device__ __forceinline__ void mma16816bf(float* c, uint32_t a0, uint32_t a1,
                                           uint32_t a2, uint32_t a3,
                                           uint32_t b0, uint32_t b1) {
    asm volatile(
        "mma.sync.aligned.m16n8k16.row.col.f32.bf16.bf16.f32 "
        "{%0,%1,%2,%3}, {%4,%5,%6,%7}, {%8,%9}, {%0,%1,%2,%3};"
        : "+f"(c[0]), "+f"(c[1]), "+f"(c[2]), "+f"(c[3])
        : "r"(a0), "r"(a1), "r"(a2), "r"(a3), "r"(b0), "r"(b1));
}
__device__ __forceinline__ void mma16816f(float* c, uint32_t a0, uint32_t a1,
                                          uint32_t a2, uint32_t a3,
                                          uint32_t b0, uint32_t b1) {
    asm volatile(
        "mma.sync.aligned.m16n8k16.row.col.f32.f16.f16.f32 "
        "{%0,%1,%2,%3}, {%4,%5,%6,%7}, {%8,%9}, {%0,%1,%2,%3};"
        : "+f"(c[0]), "+f"(c[1]), "+f"(c[2]), "+f"(c[3])
        : "r"(a0), "r"(a1), "r"(a2), "r"(a3), "r"(b0), "r"(b1));
}

__global__ __launch_bounds__(512, 1) __cluster_dims__(2, 1, 1)
void sinkhorn_fused(float* __restrict__ out)
{
    extern __shared__ unsigned char sm[];
    __half* Ks   = (__half*)(sm + SK_KS);      // [128][256] local rows of K'
    float*  recv = (float*)(sm + SK_RECV);
    float*  v    = (float*)(sm + SK_V);
    float*  u    = (float*)(sm + SK_U);
    __half* uh   = (__half*)(sm + SK_UH);
    __half* vh   = (__half*)(sm + SK_VH);
    float*  red  = (float*)(sm + SK_RED);
    float*  invp = (float*)(sm + SK_INVP);
    float*  invt = (float*)(sm + SK_INVT);
    __nv_bfloat16* As = (__nv_bfloat16*)(sm + SK_A);
    __nv_bfloat16* Bs = (__nv_bfloat16*)(sm + SK_B);

    const int rank = blockIdx.x & 1;
    const int b    = blockIdx.x >> 1;
    const int tid  = threadIdx.x;
    const int w    = tid >> 5, lane = tid & 31;
    const int lr4  = lane >> 2, lj = lane & 3;

    const uint32_t mbar_local = smem_u32(sm + SK_MBAR);
    uint32_t recv_peer, mbar_peer;
    {
        const uint32_t recv_local = smem_u32(recv);
        asm("mapa.shared::cluster.u32 %0, %1, %2;" : "=r"(recv_peer)
            : "r"(recv_local), "r"(rank ^ 1));
        asm("mapa.shared::cluster.u32 %0, %1, %2;" : "=r"(mbar_peer)
            : "r"(mbar_local), "r"(rank ^ 1));
    }
    if (tid == 0) {
        asm volatile("mbarrier.init.shared.b64 [%0], %1;"
                     :: "r"(mbar_local), "r"(64u) : "memory");
    }

    // ---- inverse norms from g_pss (fixed order: hf0 + hf1)
    if (tid < 128) {
        const float* ps = g_pss + (((size_t)b) * NT + rank * 128 + tid) * 2;
        invp[tid] = __fdividef(1.0f, fmaxf(sqrtf(ps[0] + ps[1]), 1e-12f));
    }
    if (tid < 256) {
        const float* ps = g_pss + (((size_t)NB + b) * NT + tid) * 2;
        invt[tid] = __fdividef(1.0f, fmaxf(sqrtf(ps[0] + ps[1]), 1e-12f));
        v[tid] = 1.0f; vh[tid] = __float2half_rn(1.0f);
    }

    // ---- load A tile (my 128 pred rows) into SPAD smem
    const uint4* __restrict__ Ag =
        (const uint4*)(g_tok + ((size_t)b * NT + (size_t)rank * 128) * NC);
    #pragma unroll
    for (int it = 0; it < 8; ++it) {
        const int idx = tid + it * 512;
        *(uint4*)(As + (idx >> 5) * SPAD + (idx & 31) * 8) = Ag[idx];
    }

    // ================= COST PHASE: K' -> Ks, two 128-col half-phases ========
    const int rt_c = w >> 1;          // row tile 0..7 (rows rt_c*16..+15)
    const int hc   = w & 1;           // 64-col sub-half within phase
    const __nv_bfloat16* A0 = As + (rt_c * 16 + lr4) * SPAD + lj * 2;
    const __nv_bfloat16* A8 = A0 + 8 * SPAD;
    const float ip0 = (tid < 512) ? 0.0f : 0.0f;   // placeholder (set below)

    #pragma unroll
    for (int h = 0; h < 2; ++h) {
        // load B half (target rows h*128..+128)
        const uint4* __restrict__ Bg =
            (const uint4*)(g_tok + (((size_t)NB + b) * NT + (size_t)h * 128) * NC);
        #pragma unroll
        for (int it = 0; it < 8; ++it) {
            const int idx = tid + it * 512;
            *(uint4*)(Bs + (idx >> 5) * SPAD + (idx & 31) * 8) = Bg[idx];
        }
        __syncthreads();   // A(+invp/invt on h=0) and B half visible

        float c[8][4];
        #pragma unroll
        for (int nt = 0; nt < 8; ++nt)
            c[nt][0] = c[nt][1] = c[nt][2] = c[nt][3] = 0.0f;

        #pragma unroll
        for (int kc = 0; kc < 16; ++kc) {
            const int ko = kc * 16;
            const uint32_t a0 = *(const uint32_t*)(A0 + ko);
            const uint32_t a1 = *(const uint32_t*)(A8 + ko);
            const uint32_t a2 = *(const uint32_t*)(A0 + ko + 8);
            const uint32_t a3 = *(const uint32_t*)(A8 + ko + 8);
            #pragma unroll
            for (int nt = 0; nt < 8; ++nt) {
                const __nv_bfloat16* bp =
                    Bs + (hc * 64 + nt * 8 + lr4) * SPAD + ko + lj * 2;
                mma16816bf(c[nt], a0, a1, a2, a3,
                           *(const uint32_t*)bp, *(const uint32_t*)(bp + 8));
            }
        }

        // epilogue: normalize + exp2 -> Ks
        const float p0 = invp[rt_c * 16 + lr4];
        const float p8 = invp[rt_c * 16 + 8 + lr4];
        __half* K0 = Ks + (size_t)(rt_c * 16 + lr4) * NT;
        __half* K8 = K0 + 8 * NT;
        #pragma unroll
        for (int nt = 0; nt < 8; ++nt) {
            const int col = h * 128 + hc * 64 + nt * 8 + lj * 2;
            const float it0 = invt[col], it1 = invt[col + 1];
            const float d00 = c[nt][0] * p0 * it0, d01 = c[nt][1] * p0 * it1;
            const float d80 = c[nt][2] * p8 * it0, d81 = c[nt][3] * p8 * it1;
            *(__half2*)(K0 + col) = __halves2half2(
                __float2half_rn(exp2f(fmaf(d00 - 1.0f, K2C, SHIFTF))),
                __float2half_rn(exp2f(fmaf(d01 - 1.0f, K2C, SHIFTF))));
            *(__half2*)(K8 + col) = __halves2half2(
                __float2half_rn(exp2f(fmaf(d80 - 1.0f, K2C, SHIFTF))),
                __float2half_rn(exp2f(fmaf(d81 - 1.0f, K2C, SHIFTF))));
        }
        __syncthreads();   // Ks half done; safe to overwrite Bs next phase
    }
    (void)ip0;

    // cluster sync: peer mbarrier init + (independent) Ks ready
    asm volatile("barrier.cluster.arrive.aligned;" ::: "memory");
    asm volatile("barrier.cluster.wait.aligned;" ::: "memory");

    // ================= SINKHORN (round-14 exact, on smem Ks) ================
    uint32_t frag[64];
    const bool roww = (w < 8);
    const int rt = w;           // row warp: rows rt*16..+15
    const int wc = w - 8;       // col warp: m-tiles (cols) 2wc, 2wc+1

    if (roww) {
        #pragma unroll
        for (int t = 0; t < 16; ++t) {
            const int kt = t * 16 + 2 * lj;
            frag[t*4+0] = *(const uint32_t*)&Ks[(rt * 16 + lr4) * NT + kt];
            frag[t*4+1] = *(const uint32_t*)&Ks[(rt * 16 + 8 + lr4) * NT + kt];
            frag[t*4+2] = *(const uint32_t*)&Ks[(rt * 16 + lr4) * NT + kt + 8];
            frag[t*4+3] = *(const uint32_t*)&Ks[(rt * 16 + 8 + lr4) * NT + kt + 8];
        }
    } else {
        #pragma unroll
        for (int mt = 0; mt < 2; ++mt) {
            const int j0 = (2 * wc + mt) * 16 + lr4;
            const int j1 = j0 + 8;
            #pragma unroll
            for (int t = 0; t < 8; ++t) {
                const int k0 = t * 16 + 2 * lj;
                frag[(mt*8+t)*4+0] = h2_as_u32(Ks[(size_t)k0 * NT + j0],
                                               Ks[(size_t)(k0 + 1) * NT + j0]);
                frag[(mt*8+t)*4+1] = h2_as_u32(Ks[(size_t)k0 * NT + j1],
                                               Ks[(size_t)(k0 + 1) * NT + j1]);
                frag[(mt*8+t)*4+2] = h2_as_u32(Ks[(size_t)(k0 + 8) * NT + j0],
                                               Ks[(size_t)(k0 + 9) * NT + j0]);
                frag[(mt*8+t)*4+3] = h2_as_u32(Ks[(size_t)(k0 + 8) * NT + j1],
                                               Ks[(size_t)(k0 + 9) * NT + j1]);
            }
        }
    }

    for (int it = 0; it < NITER; ++it) {
        __syncthreads();   // vh(it) visible to row warps
        if (roww) {
            float cc[4][4] = {};
            #pragma unroll
            for (int t = 0; t < 16; t += 4) {
                #pragma unroll
                for (int q = 0; q < 4; ++q) {
                    const int kt = (t + q) * 16 + 2 * lj;
                    mma16816f(cc[q],
                              frag[(t+q)*4+0], frag[(t+q)*4+1],
                              frag[(t+q)*4+2], frag[(t+q)*4+3],
                              *(const uint32_t*)&vh[kt],
                              *(const uint32_t*)&vh[kt + 8]);
                }
            }
            if (lj == 0) {
                const float s0 = (cc[0][0] + cc[1][0]) + (cc[2][0] + cc[3][0]);
                const float s2 = (cc[0][2] + cc[1][2]) + (cc[2][2] + cc[3][2]);
                const float u0 = __fdividef(MUC, s0);
                const float u2 = __fdividef(MUC, s2);
                const int i0 = rt * 16 + lr4;
                u[i0] = u0;      uh[i0] = __float2half_rn(u0 * 64.0f);
                u[i0 + 8] = u2;  uh[i0 + 8] = __float2half_rn(u2 * 64.0f);
            }
        }
        __syncthreads();   // uh visible to col warps
        if (!roww) {
            const int buf = it & 1;
            float cc[2][4] = {};
            #pragma unroll
            for (int t = 0; t < 8; ++t) {
                const int k0 = t * 16 + 2 * lj;
                const uint32_t b0 = *(const uint32_t*)&uh[k0];
                const uint32_t b1 = *(const uint32_t*)&uh[k0 + 8];
                #pragma unroll
                for (int mt = 0; mt < 2; ++mt)
                    mma16816f(cc[mt],
                              frag[(mt*8+t)*4+0], frag[(mt*8+t)*4+1],
                              frag[(mt*8+t)*4+2], frag[(mt*8+t)*4+3],
                              b0, b1);
            }
            if (lj == 0) {
                #pragma unroll
                for (int mt = 0; mt < 2; ++mt) {
                    const int j0 = (2 * wc + mt) * 16 + lr4;
                    asm volatile("st.shared::cluster.b32 [%0], %1;"
                                 :: "r"(recv_peer + (uint32_t)((buf * NT + j0) * 4)),
                                    "f"(cc[mt][0]) : "memory");
                    asm volatile("st.shared::cluster.b32 [%0], %1;"
                                 :: "r"(recv_peer + (uint32_t)((buf * NT + j0 + 8) * 4)),
                                    "f"(cc[mt][2]) : "memory");
                }
                asm volatile("mbarrier.arrive.release.cluster.shared::cluster.b64 _, [%0];"
                             :: "r"(mbar_peer) : "memory");
                uint32_t done;
                asm volatile("{ .reg .pred p; "
                             "mbarrier.try_wait.parity.acquire.cluster.shared::cta.b64 p, [%1], %2; "
                             "selp.b32 %0, 1, 0, p; }"
                             : "=r"(done) : "r"(mbar_local), "r"((uint32_t)buf) : "memory");
                while (!done) {
                    asm volatile("{ .reg .pred p; "
                                 "mbarrier.try_wait.parity.acquire.cluster.shared::cta.b64 p, [%1], %2, 0x989680; "
                                 "selp.b32 %0, 1, 0, p; }"
                                 : "=r"(done) : "r"(mbar_local), "r"((uint32_t)buf) : "memory");
                }
                #pragma unroll
                for (int mt = 0; mt < 2; ++mt) {
                    const int j0 = (2 * wc + mt) * 16 + lr4;
                    const float p0 = recv[buf * NT + j0];
                    const float p1 = recv[buf * NT + j0 + 8];
                    const float s0 = rank == 0 ? (cc[mt][0] + p0) : (p0 + cc[mt][0]);
                    const float s1 = rank == 0 ? (cc[mt][2] + p1) : (p1 + cc[mt][2]);
                    const float nv0 = __fdividef(0.25f, s0);   // MUC*64 (uh scale cancels)
                    const float nv1 = __fdividef(0.25f, s1);
                    v[j0] = nv0;     vh[j0] = __float2half_rn(nv0);
                    v[j0 + 8] = nv1; vh[j0 + 8] = __float2half_rn(nv1);
                }
            }
        }
    }
    __syncthreads();   // final u, v visible to all

    // ---- transport loss over my 128 rows (warp w -> rows 8w..8w+7)
    float vl[8];
    {
        const float4 v0 = *(const float4*)&v[lane * 8];
        const float4 v1 = *(const float4*)&v[lane * 8 + 4];
        vl[0]=v0.x; vl[1]=v0.y; vl[2]=v0.z; vl[3]=v0.w;
        vl[4]=v1.x; vl[5]=v1.y; vl[6]=v1.z; vl[7]=v1.w;
    }
    float acc = 0.0f;
    #pragma unroll
    for (int r = 0; r < 8; ++r) {
        const int i = w * 8 + r;
        const float ui = u[i];
        const uint4 kw = *(const uint4*)(Ks + (size_t)i * NT + lane * 8);
        float kf[8];
        {
            float2 f;
            f = __half22float2(*(const __half2*)&kw.x); kf[0]=f.x; kf[1]=f.y;
            f = __half22float2(*(const __half2*)&kw.y); kf[2]=f.x; kf[3]=f.y;
            f = __half22float2(*(const __half2*)&kw.z); kf[4]=f.x; kf[5]=f.y;
            f = __half22float2(*(const __half2*)&kw.w); kf[6]=f.x; kf[7]=f.y;
        }
        #pragma unroll
        for (int q = 0; q < 8; ++q) {
            const float k = kf[q];
            if (k > 0.0f) {
                const float cost = (SHIFTF - __log2f(k)) * INV_K2;  // == 1 - dot
                acc = fmaf(ui * k * vl[q], cost, acc);
            }
        }
    }
    #pragma unroll
    for (int o = 16; o; o >>= 1) acc += __shfl_xor_sync(0xffffffffu, acc, o);
    if (lane == 0) red[w] = acc;
    __syncthreads();
    if (w == 0) {
        float s = (lane < 16) ? red[lane] : 0.0f;
        #pragma unroll
        for (int o = 16; o; o >>= 1) s += __shfl_xor_sync(0xffffffffu, s, o);
        if (lane == 0) {
            g_part[blockIdx.x] = s;
            __threadfence();
            if (atomicAdd(&g_ctr, 1u) == 2 * NB - 1) {   // last CTA: deterministic mean
                __threadfence();
                float tot = 0.0f;
                #pragma unroll
                for (int i = 0; i < 2 * NB; ++i) tot += __ldcg(&g_part[i]);
                out[0] = tot * (1.0f / NB);
            }
        }
    }
    // no CTA may exit while peer pushes could still target its smem
    asm volatile("barrier.cluster.arrive.aligned;" ::: "memory");
    asm volatile("barrier.cluster.wait.aligned;" ::: "memory");
}

// ============================================================================
extern "C" void kernel_launch(void* const* d_in, const int* in_sizes, int n_in,
                              void* d_out, int out_size)
{
    const float* pred = (const float*)d_in[0];
    const float* tgt  = (const float*)d_in[1];
    float* out = (float*)d_out;

    cudaFuncSetAttribute(gather_kernel, cudaFuncAttributeMaxDynamicSharedMemorySize, GK_SMEM);
    gather_kernel<<<dim3(NB, 2, 2), 1024, GK_SMEM>>>(pred, tgt);

    cudaFuncSetAttribute(sinkhorn_fused, cudaFuncAttributeMaxDynamicSharedMemorySize, SK_SMEM);
    sinkhorn_fused<<<2 * NB, 512, SK_SMEM>>>(out);
}

// round 17
// speedup vs baseline: 1.0544x; 1.0425x over previous
#include <cuda_runtime.h>
#include <cuda_fp16.h>
#include <cuda_bf16.h>
#include <cstdint>

// ---------------- problem constants ----------------
#define NB   64
#define NT   256
#define NC   256
#define HW   4096
#define NITER 30

#define K2C     28.853900817779268f   // log2(e)/eps
#define INV_K2  0.03465735902799727f  // eps*ln2
#define SHIFTF  26.0f
#define MUC     (1.0f/256.0f)

// ---------------- scratch ----------------
__device__ __align__(16) __nv_bfloat16 g_tok[(size_t)2 * NB * NT * NC];  // [z][b][i][c] RAW
__device__ __align__(16) float         g_pss[(size_t)2 * NB * NT];       // [z][b][i] sumsq
__device__ float    g_part[2 * NB];
__device__ unsigned g_ctr;

__device__ __forceinline__ uint32_t smem_u32(const void* p) {
    uint32_t a;
    asm("{ .reg .u64 t; cvta.to.shared.u64 t, %1; cvt.u32.u64 %0, t; }" : "=r"(a) : "l"(p));
    return a;
}
__device__ __forceinline__ uint32_t h2_as_u32(__half lo, __half hi) {
    union { __half2 h; uint32_t u; } c;
    c.h = __halves2half2(lo, hi);
    return c.u;
}

// ============================================================================
// Kernel 1: page-local SECTOR gather.  grid (64, 2), 1024 threads.
// Warp w has fixed token group g=w&7 (lane -> token i=g*32+lane, sample col s
// computed once); it walks 64 channel rows (c = 4t + (w>>3)), each warp read
// spanning ~2KB of one DRAM row with one 32B sector per lane.
// Reads ~268MB of sectors instead of streaming the full 537MB.
// ============================================================================
#define TSTR 264
#define GK_SMEM (256 * TSTR * 2 + 4096)

__global__ __launch_bounds__(1024, 1) void gather_kernel(
    const float* __restrict__ pred, const float* __restrict__ tgt)
{
    extern __shared__ unsigned char sm[];
    __nv_bfloat16* T = (__nv_bfloat16*)sm;               // [256 c][264] swizzled
    float* pss = (float*)(sm + 256 * TSTR * 2);          // [4][256]

    const int b = blockIdx.x, z = blockIdx.y;
    if (threadIdx.x == 0 && (b | z) == 0) g_ctr = 0u;
    const int tid = threadIdx.x;
    const int w = tid >> 5, lane = tid & 31;
    const float DELTA = 4095.0f / 255.0f;

    const float* __restrict__ src = (z ? tgt : pred) + (size_t)b * NC * HW;

    // fixed token for this lane: group w&7, lane offset
    const int i  = (w & 7) * 32 + lane;
    const int s  = (int)(__fmul_rn((float)i, DELTA));    // exact ref truncation
    const int coff = w >> 3;                              // channel offset 0..3
    const int ib = i >> 3, io = i & 7;

    #pragma unroll
    for (int t8 = 0; t8 < 64; t8 += 8) {
        float x[8];
        #pragma unroll
        for (int j = 0; j < 8; ++j) {
            const int c = (t8 + j) * 4 + coff;
            x[j] = __ldcs(src + (size_t)c * HW + s);
        }
        #pragma unroll
        for (int j = 0; j < 8; ++j) {
            const int c = (t8 + j) * 4 + coff;
            T[c * TSTR + ((ib ^ ((c >> 3) & 7)) << 3) + io] = __float2bfloat16(x[j]);
        }
    }
    __syncthreads();

    {   // sum of squares per token over all 256 channels (4 partials)
        const int i2 = tid & 255, part = tid >> 8;
        const int ib2 = i2 >> 3, io2 = i2 & 7;
        float ss = 0.0f;
        #pragma unroll 8
        for (int cc = 0; cc < 64; ++cc) {
            const int c = part * 64 + cc;
            const float xx = __bfloat162float(
                T[c * TSTR + ((ib2 ^ ((c >> 3) & 7)) << 3) + io2]);
            ss = fmaf(xx, xx, ss);
        }
        pss[part * 256 + i2] = ss;
    }
    __syncthreads();
    if (tid < 256) {
        g_pss[((size_t)z * NB + b) * NT + tid] =
            (pss[tid] + pss[256 + tid]) + (pss[512 + tid] + pss[768 + tid]);
    }

    // RAW token-major write: 256 tokens x 256 ch bf16 = 8192 uint4, 8/thread
    uint4* __restrict__ dst = (uint4*)(g_tok + ((size_t)z * NB + b) * NT * NC);
    #pragma unroll
    for (int k = 0; k < 8; ++k) {
        const int idx = tid + k * 1024;
        const int ii = idx >> 5, c0 = (idx & 31) * 8;
        const int ib2 = ii >> 3, io2 = ii & 7;
        union { uint4 u; __nv_bfloat16 h[8]; } o;
        #pragma unroll
        for (int j = 0; j < 8; ++j) {
            const int c = c0 + j;
            o.h[j] = T[c * TSTR + ((ib2 ^ ((c >> 3) & 7)) << 3) + io2];
        }
        dst[idx] = o.u;
    }
}

// ============================================================================
// Kernel 2: FUSED cost GEMM + Sinkhorn (round-16 exact; g_pss now 1 float/token).
// ============================================================================
#define SPAD 264
#define SK_KS    0
#define SK_RECV  65536
#define SK_V     (SK_RECV + 2048)
#define SK_U     (SK_V + 1024)
#define SK_UH    (SK_U + 512)
#define SK_VH    (SK_UH + 256)
#define SK_RED   (SK_VH + 512)
#define SK_MBAR  (SK_RED + 128)
#define SK_INVP  (SK_MBAR + 16)
#define SK_INVT  (SK_INVP + 512)
#define SK_A     (SK_INVT + 1024)
#define SK_B     (SK_A + 128 * SPAD * 2)
#define SK_SMEM  (SK_B + 128 * SPAD * 2)

__device__ __forceinline__ void mma16816bf(float* c, uint32_t a0, uint32_t a1,
                                           uint32_t a2, uint32_t a3,
                                           uint32_t b0, uint32_t b1) {
    asm volatile(
        "mma.sync.aligned.m16n8k16.row.col.f32.bf16.bf16.f32 "
        "{%0,%1,%2,%3}, {%4,%5,%6,%7}, {%8,%9}, {%0,%1,%2,%3};"
        : "+f"(c[0]), "+f"(c[1]), "+f"(c[2]), "+f"(c[3])
        : "r"(a0), "r"(a1), "r"(a2), "r"(a3), "r"(b0), "r"(b1));
}
__device__ __forceinline__ void mma16816f(float* c, uint32_t a0, uint32_t a1,
                                          uint32_t a2, uint32_t a3,
                                          uint32_t b0, uint32_t b1) {
    asm volatile(
        "mma.sync.aligned.m16n8k16.row.col.f32.f16.f16.f32 "
        "{%0,%1,%2,%3}, {%4,%5,%6,%7}, {%8,%9}, {%0,%1,%2,%3};"
        : "+f"(c[0]), "+f"(c[1]), "+f"(c[2]), "+f"(c[3])
        : "r"(a0), "r"(a1), "r"(a2), "r"(a3), "r"(b0), "r"(b1));
}

__global__ __launch_bounds__(512, 1) __cluster_dims__(2, 1, 1)
void sinkhorn_fused(float* __restrict__ out)
{
    extern __shared__ unsigned char sm[];
    __half* Ks   = (__half*)(sm + SK_KS);      // [128][256] local rows of K'
    float*  recv = (float*)(sm + SK_RECV);
    float*  v    = (float*)(sm + SK_V);
    float*  u    = (float*)(sm + SK_U);
    __half* uh   = (__half*)(sm + SK_UH);
    __half* vh   = (__half*)(sm + SK_VH);
    float*  red  = (float*)(sm + SK_RED);
    float*  invp = (float*)(sm + SK_INVP);
    float*  invt = (float*)(sm + SK_INVT);
    __nv_bfloat16* As = (__nv_bfloat16*)(sm + SK_A);
    __nv_bfloat16* Bs = (__nv_bfloat16*)(sm + SK_B);

    const int rank = blockIdx.x & 1;
    const int b    = blockIdx.x >> 1;
    const int tid  = threadIdx.x;
    const int w    = tid >> 5, lane = tid & 31;
    const int lr4  = lane >> 2, lj = lane & 3;

    const uint32_t mbar_local = smem_u32(sm + SK_MBAR);
    uint32_t recv_peer, mbar_peer;
    {
        const uint32_t recv_local = smem_u32(recv);
        asm("mapa.shared::cluster.u32 %0, %1, %2;" : "=r"(recv_peer)
            : "r"(recv_local), "r"(rank ^ 1));
        asm("mapa.shared::cluster.u32 %0, %1, %2;" : "=r"(mbar_peer)
            : "r"(mbar_local), "r"(rank ^ 1));
    }
    if (tid == 0) {
        asm volatile("mbarrier.init.shared.b64 [%0], %1;"
                     :: "r"(mbar_local), "r"(64u) : "memory");
    }

    // ---- inverse norms from g_pss
    if (tid < 128) {
        const float ps = g_pss[(size_t)b * NT + rank * 128 + tid];
        invp[tid] = __fdividef(1.0f, fmaxf(sqrtf(ps), 1e-12f));
    }
    if (tid < 256) {
        const float ps = g_pss[((size_t)NB + b) * NT + tid];
        invt[tid] = __fdividef(1.0f, fmaxf(sqrtf(ps), 1e-12f));
        v[tid] = 1.0f; vh[tid] = __float2half_rn(1.0f);
    }

    // ---- load A tile (my 128 pred rows)
    const uint4* __restrict__ Ag =
        (const uint4*)(g_tok + ((size_t)b * NT + (size_t)rank * 128) * NC);
    #pragma unroll
    for (int it = 0; it < 8; ++it) {
        const int idx = tid + it * 512;
        *(uint4*)(As + (idx >> 5) * SPAD + (idx & 31) * 8) = Ag[idx];
    }

    // ================= COST PHASE: K' -> Ks, two 128-col half-phases ========
    const int rt_c = w >> 1;
    const int hc   = w & 1;
    const __nv_bfloat16* A0 = As + (rt_c * 16 + lr4) * SPAD + lj * 2;
    const __nv_bfloat16* A8 = A0 + 8 * SPAD;

    #pragma unroll
    for (int h = 0; h < 2; ++h) {
        const uint4* __restrict__ Bg =
            (const uint4*)(g_tok + (((size_t)NB + b) * NT + (size_t)h * 128) * NC);
        #pragma unroll
        for (int it = 0; it < 8; ++it) {
            const int idx = tid + it * 512;
            *(uint4*)(Bs + (idx >> 5) * SPAD + (idx & 31) * 8) = Bg[idx];
        }
        __syncthreads();

        float c[8][4];
        #pragma unroll
        for (int nt = 0; nt < 8; ++nt)
            c[nt][0] = c[nt][1] = c[nt][2] = c[nt][3] = 0.0f;

        #pragma unroll
        for (int kc = 0; kc < 16; ++kc) {
            const int ko = kc * 16;
            const uint32_t a0 = *(const uint32_t*)(A0 + ko);
            const uint32_t a1 = *(const uint32_t*)(A8 + ko);
            const uint32_t a2 = *(const uint32_t*)(A0 + ko + 8);
            const uint32_t a3 = *(const uint32_t*)(A8 + ko + 8);
            #pragma unroll
            for (int nt = 0; nt < 8; ++nt) {
                const __nv_bfloat16* bp =
                    Bs + (hc * 64 + nt * 8 + lr4) * SPAD + ko + lj * 2;
                mma16816bf(c[nt], a0, a1, a2, a3,
                           *(const uint32_t*)bp, *(const uint32_t*)(bp + 8));
            }
        }

        const float p0 = invp[rt_c * 16 + lr4];
        const float p8 = invp[rt_c * 16 + 8 + lr4];
        __half* K0 = Ks + (size_t)(rt_c * 16 + lr4) * NT;
        __half* K8 = K0 + 8 * NT;
        #pragma unroll
        for (int nt = 0; nt < 8; ++nt) {
            const int col = h * 128 + hc * 64 + nt * 8 + lj * 2;
            const float it0 = invt[col], it1 = invt[col + 1];
            const float d00 = c[nt][0] * p0 * it0, d01 = c[nt][1] * p0 * it1;
            const float d80 = c[nt][2] * p8 * it0, d81 = c[nt][3] * p8 * it1;
            *(__half2*)(K0 + col) = __halves2half2(
                __float2half_rn(exp2f(fmaf(d00 - 1.0f, K2C, SHIFTF))),
                __float2half_rn(exp2f(fmaf(d01 - 1.0f, K2C, SHIFTF))));
            *(__half2*)(K8 + col) = __halves2half2(
                __float2half_rn(exp2f(fmaf(d80 - 1.0f, K2C, SHIFTF))),
                __float2half_rn(exp2f(fmaf(d81 - 1.0f, K2C, SHIFTF))));
        }
        __syncthreads();
    }

    // cluster sync: peer mbarrier init + Ks ready
    asm volatile("barrier.cluster.arrive.aligned;" ::: "memory");
    asm volatile("barrier.cluster.wait.aligned;" ::: "memory");

    // ================= SINKHORN (round-14 exact, on smem Ks) ================
    uint32_t frag[64];
    const bool roww = (w < 8);
    const int rt = w;
    const int wc = w - 8;

    if (roww) {
        #pragma unroll
        for (int t = 0; t < 16; ++t) {
            const int kt = t * 16 + 2 * lj;
            frag[t*4+0] = *(const uint32_t*)&Ks[(rt * 16 + lr4) * NT + kt];
            frag[t*4+1] = *(const uint32_t*)&Ks[(rt * 16 + 8 + lr4) * NT + kt];
            frag[t*4+2] = *(const uint32_t*)&Ks[(rt * 16 + lr4) * NT + kt + 8];
            frag[t*4+3] = *(const uint32_t*)&Ks[(rt * 16 + 8 + lr4) * NT + kt + 8];
        }
    } else {
        #pragma unroll
        for (int mt = 0; mt < 2; ++mt) {
            const int j0 = (2 * wc + mt) * 16 + lr4;
            const int j1 = j0 + 8;
            #pragma unroll
            for (int t = 0; t < 8; ++t) {
                const int k0 = t * 16 + 2 * lj;
                frag[(mt*8+t)*4+0] = h2_as_u32(Ks[(size_t)k0 * NT + j0],
                                               Ks[(size_t)(k0 + 1) * NT + j0]);
                frag[(mt*8+t)*4+1] = h2_as_u32(Ks[(size_t)k0 * NT + j1],
                                               Ks[(size_t)(k0 + 1) * NT + j1]);
                frag[(mt*8+t)*4+2] = h2_as_u32(Ks[(size_t)(k0 + 8) * NT + j0],
                                               Ks[(size_t)(k0 + 9) * NT + j0]);
                frag[(mt*8+t)*4+3] = h2_as_u32(Ks[(size_t)(k0 + 8) * NT + j1],
                                               Ks[(size_t)(k0 + 9) * NT + j1]);
            }
        }
    }

    for (int it = 0; it < NITER; ++it) {
        __syncthreads();
        if (roww) {
            float cc[4][4] = {};
            #pragma unroll
            for (int t = 0; t < 16; t += 4) {
                #pragma unroll
                for (int q = 0; q < 4; ++q) {
                    const int kt = (t + q) * 16 + 2 * lj;
                    mma16816f(cc[q],
                              frag[(t+q)*4+0], frag[(t+q)*4+1],
                              frag[(t+q)*4+2], frag[(t+q)*4+3],
                              *(const uint32_t*)&vh[kt],
                              *(const uint32_t*)&vh[kt + 8]);
                }
            }
            if (lj == 0) {
                const float s0 = (cc[0][0] + cc[1][0]) + (cc[2][0] + cc[3][0]);
                const float s2 = (cc[0][2] + cc[1][2]) + (cc[2][2] + cc[3][2]);
                const float u0 = __fdividef(MUC, s0);
                const float u2 = __fdividef(MUC, s2);
                const int i0 = rt * 16 + lr4;
                u[i0] = u0;      uh[i0] = __float2half_rn(u0 * 64.0f);
                u[i0 + 8] = u2;  uh[i0 + 8] = __float2half_rn(u2 * 64.0f);
            }
        }
        __syncthreads();
        if (!roww) {
            const int buf = it & 1;
            float cc[2][4] = {};
            #pragma unroll
            for (int t = 0; t < 8; ++t) {
                const int k0 = t * 16 + 2 * lj;
                const uint32_t b0 = *(const uint32_t*)&uh[k0];
                const uint32_t b1 = *(const uint32_t*)&uh[k0 + 8];
                #pragma unroll
                for (int mt = 0; mt < 2; ++mt)
                    mma16816f(cc[mt],
                              frag[(mt*8+t)*4+0], frag[(mt*8+t)*4+1],
                              frag[(mt*8+t)*4+2], frag[(mt*8+t)*4+3],
                              b0, b1);
            }
            if (lj == 0) {
                #pragma unroll
                for (int mt = 0; mt < 2; ++mt) {
                    const int j0 = (2 * wc + mt) * 16 + lr4;
                    asm volatile("st.shared::cluster.b32 [%0], %1;"
                                 :: "r"(recv_peer + (uint32_t)((buf * NT + j0) * 4)),
                                    "f"(cc[mt][0]) : "memory");
                    asm volatile("st.shared::cluster.b32 [%0], %1;"
                                 :: "r"(recv_peer + (uint32_t)((buf * NT + j0 + 8) * 4)),
                                    "f"(cc[mt][2]) : "memory");
                }
                asm volatile("mbarrier.arrive.release.cluster.shared::cluster.b64 _, [%0];"
                             :: "r"(mbar_peer) : "memory");
                uint32_t done;
                asm volatile("{ .reg .pred p; "
                             "mbarrier.try_wait.parity.acquire.cluster.shared::cta.b64 p, [%1], %2; "
                             "selp.b32 %0, 1, 0, p; }"
                             : "=r"(done) : "r"(mbar_local), "r"((uint32_t)buf) : "memory");
                while (!done) {
                    asm volatile("{ .reg .pred p; "
                                 "mbarrier.try_wait.parity.acquire.cluster.shared::cta.b64 p, [%1], %2, 0x989680; "
                                 "selp.b32 %0, 1, 0, p; }"
                                 : "=r"(done) : "r"(mbar_local), "r"((uint32_t)buf) : "memory");
                }
                #pragma unroll
                for (int mt = 0; mt < 2; ++mt) {
                    const int j0 = (2 * wc + mt) * 16 + lr4;
                    const float p0 = recv[buf * NT + j0];
                    const float p1 = recv[buf * NT + j0 + 8];
                    const float s0 = rank == 0 ? (cc[mt][0] + p0) : (p0 + cc[mt][0]);
                    const float s1 = rank == 0 ? (cc[mt][2] + p1) : (p1 + cc[mt][2]);
                    const float nv0 = __fdividef(0.25f, s0);   // MUC*64 (uh scale cancels)
                    const float nv1 = __fdividef(0.25f, s1);
                    v[j0] = nv0;     vh[j0] = __float2half_rn(nv0);
                    v[j0 + 8] = nv1; vh[j0 + 8] = __float2half_rn(nv1);
                }
            }
        }
    }
    __syncthreads();

    // ---- transport loss over my 128 rows (warp w -> rows 8w..8w+7)
    float vl[8];
    {
        const float4 v0 = *(const float4*)&v[lane * 8];
        const float4 v1 = *(const float4*)&v[lane * 8 + 4];
        vl[0]=v0.x; vl[1]=v0.y; vl[2]=v0.z; vl[3]=v0.w;
        vl[4]=v1.x; vl[5]=v1.y; vl[6]=v1.z; vl[7]=v1.w;
    }
    float acc = 0.0f;
    #pragma unroll
    for (int r = 0; r < 8; ++r) {
        const int i = w * 8 + r;
        const float ui = u[i];
        const uint4 kw = *(const uint4*)(Ks + (size_t)i * NT + lane * 8);
        float kf[8];
        {
            float2 f;
            f = __half22float2(*(const __half2*)&kw.x); kf[0]=f.x; kf[1]=f.y;
            f = __half22float2(*(const __half2*)&kw.y); kf[2]=f.x; kf[3]=f.y;
            f = __half22float2(*(const __half2*)&kw.z); kf[4]=f.x; kf[5]=f.y;
            f = __half22float2(*(const __half2*)&kw.w); kf[6]=f.x; kf[7]=f.y;
        }
        #pragma unroll
        for (int q = 0; q < 8; ++q) {
            const float k = kf[q];
            if (k > 0.0f) {
                const float cost = (SHIFTF - __log2f(k)) * INV_K2;  // == 1 - dot
                acc = fmaf(ui * k * vl[q], cost, acc);
            }
        }
    }
    #pragma unroll
    for (int o = 16; o; o >>= 1) acc += __shfl_xor_sync(0xffffffffu, acc, o);
    if (lane == 0) red[w] = acc;
    __syncthreads();
    if (w == 0) {
        float s = (lane < 16) ? red[lane] : 0.0f;
        #pragma unroll
        for (int o = 16; o; o >>= 1) s += __shfl_xor_sync(0xffffffffu, s, o);
        if (lane == 0) {
            g_part[blockIdx.x] = s;
            __threadfence();
            if (atomicAdd(&g_ctr, 1u) == 2 * NB - 1) {   // last CTA: deterministic mean
                __threadfence();
                float tot = 0.0f;
                #pragma unroll
                for (int i = 0; i < 2 * NB; ++i) tot += __ldcg(&g_part[i]);
                out[0] = tot * (1.0f / NB);
            }
        }
    }
    asm volatile("barrier.cluster.arrive.aligned;" ::: "memory");
    asm volatile("barrier.cluster.wait.aligned;" ::: "memory");
}

// ============================================================================
extern "C" void kernel_launch(void* const* d_in, const int* in_sizes, int n_in,
                              void* d_out, int out_size)
{
    const float* pred = (const float*)d_in[0];
    const float* tgt  = (const float*)d_in[1];
    float* out = (float*)d_out;

    cudaFuncSetAttribute(gather_kernel, cudaFuncAttributeMaxDynamicSharedMemorySize, GK_SMEM);
    gather_kernel<<<dim3(NB, 2), 1024, GK_SMEM>>>(pred, tgt);

    cudaFuncSetAttribute(sinkhorn_fused, cudaFuncAttributeMaxDynamicSharedMemorySize, SK_SMEM);
    sinkhorn_fused<<<2 * NB, 512, SK_SMEM>>>(out);
}